// round 8
// baseline (speedup 1.0000x reference)
#include <cuda_runtime.h>
#include <math.h>

#define NS 3
#define SYM 512
#define FD 20
#define NLIN 11
#define NOUT 9
#define HH 2048
#define HIN (NS*SYM*NOUT)   /* 13824 */
#define NO (NS*SYM)         /* 1536 */
#define EPSF 1e-9f

// ---------------- device scratch (no allocations allowed) ----------------
__device__ float g_v[HIN];
__device__ float g_ha[HH];
__device__ float g_hb[HH];
__device__ float g_o[NO];

// ---------------- front end: inorm -> DFT -> bilinear -> leaky -> softmax(NS) ----------------
__global__ __launch_bounds__(128) void k_front(const float* __restrict__ wax,
                                               const float* __restrict__ blw,
                                               const float* __restrict__ blb) {
    int s = blockIdx.x;           // 0..511
    int tid = threadIdx.x;
    int warp = tid >> 5, lane = tid & 31;

    __shared__ float sh_xn[NS][FD];
    __shared__ float sh_re[NS][NLIN], sh_im[NS][NLIN];
    __shared__ float sh_z[NS][NOUT];

    if (warp < NS) {
        int b = warp;
        float x = 0.f;
        if (lane < FD) x = wax[(b*SYM + s)*FD + lane];
        float sum = x, sq = x*x;
        #pragma unroll
        for (int o = 16; o > 0; o >>= 1) {
            sum += __shfl_xor_sync(0xffffffffu, sum, o);
            sq  += __shfl_xor_sync(0xffffffffu, sq,  o);
        }
        float m = sum * (1.0f/FD);
        float var = sq * (1.0f/FD) - m*m;
        float r = rsqrtf(var + EPSF);
        if (lane < FD) sh_xn[b][lane] = (x - m) * r;
        __syncwarp();

        if (lane < NLIN) {
            float re = 0.f, im = 0.f;
            #pragma unroll
            for (int f = 0; f < FD; f++) {
                float sn, cs;
                sincospif((float)(lane*f) * 0.1f, &sn, &cs);
                float xv = sh_xn[b][f];
                re += xv * cs;
                im -= xv * sn;
            }
            sh_re[b][lane] = re;
            sh_im[b][lane] = im;
        }
        __syncwarp();

        if (lane < NOUT) {
            int k = lane;
            float z = blb[k];
            #pragma unroll
            for (int i = 0; i < NLIN; i++) {
                float t = 0.f;
                #pragma unroll
                for (int j = 0; j < NLIN; j++)
                    t += blw[(k*NLIN + i)*NLIN + j] * sh_im[b][j];
                z += sh_re[b][i] * t;
            }
            z = (z >= 0.f) ? z : 0.01f*z;
            sh_z[b][k] = z;
        }
    }
    __syncthreads();

    if (tid < NOUT) {
        int k = tid;
        float z0 = sh_z[0][k], z1 = sh_z[1][k], z2 = sh_z[2][k];
        float m = fmaxf(z0, fmaxf(z1, z2));
        float e0 = expf(z0-m), e1 = expf(z1-m), e2 = expf(z2-m);
        float inv = 1.f/(e0+e1+e2);
        g_v[s*(NS*NOUT) + 0*NOUT + k] = e0*inv;
        g_v[s*(NS*NOUT) + 1*NOUT + k] = e1*inv;
        g_v[s*(NS*NOUT) + 2*NOUT + k] = e2*inv;
    }
}

// ---------------- L2 prefetch (cache-warm only; no data dependency) ----------------
__global__ __launch_bounds__(256) void k_pf(const float* __restrict__ p, unsigned nlines) {
    unsigned i = blockIdx.x*blockDim.x + threadIdx.x;
    unsigned stride = gridDim.x*blockDim.x;
    for (; i < nlines; i += stride)
        asm volatile("prefetch.global.L2 [%0];" :: "l"(p + (size_t)i*32) : "memory");
}

// ---------------- fused LSTM cell (zero state): block computes i,g,o rows of JPB j's ----------------
template<int NT, int MINB, int N, int JPB, bool STREAM>
__global__ __launch_bounds__(NT, MINB) void k_cell(const float* __restrict__ W,
                                                   const float* __restrict__ x,
                                                   const float* __restrict__ b_ih,
                                                   const float* __restrict__ b_hh,
                                                   float* __restrict__ h) {
    constexpr int N4   = N / 4;
    constexpr int ITER = N4 / NT;       // exact by construction
    constexpr int NR   = 3 * JPB;
    const int j0 = blockIdx.x * JPB;
    const int tid = threadIdx.x;

    const float4* __restrict__ xv = (const float4*)x;
    const float4* Wr[NR];
    #pragma unroll
    for (int q = 0; q < JPB; q++) {
        int j = j0 + q;
        Wr[3*q + 0] = (const float4*)(W + (size_t)(0*HH + j) * N);  // i
        Wr[3*q + 1] = (const float4*)(W + (size_t)(2*HH + j) * N);  // g
        Wr[3*q + 2] = (const float4*)(W + (size_t)(3*HH + j) * N);  // o
    }

    float acc[NR];
    #pragma unroll
    for (int r = 0; r < NR; r++) acc[r] = 0.f;

    #pragma unroll 6
    for (int it = 0; it < ITER; it++) {
        int t = tid + it * NT;
        float4 v = xv[t];
        #pragma unroll
        for (int r = 0; r < NR; r++) {
            float4 w = STREAM ? __ldcs(&Wr[r][t]) : Wr[r][t];
            acc[r] += w.x*v.x + w.y*v.y + w.z*v.z + w.w*v.w;
        }
    }

    __shared__ float sred[NR][NT/32];
    #pragma unroll
    for (int r = 0; r < NR; r++) {
        float a = acc[r];
        #pragma unroll
        for (int o = 16; o > 0; o >>= 1) a += __shfl_xor_sync(0xffffffffu, a, o);
        if ((tid & 31) == 0) sred[r][tid >> 5] = a;
    }
    __syncthreads();

    if (tid < JPB) {
        int q = tid, j = j0 + q;
        float gi = 0.f, gg = 0.f, go = 0.f;
        #pragma unroll
        for (int w = 0; w < NT/32; w++) {
            gi += sred[3*q + 0][w];
            gg += sred[3*q + 1][w];
            go += sred[3*q + 2][w];
        }
        gi += b_ih[j]        + b_hh[j];
        gg += b_ih[2*HH + j] + b_hh[2*HH + j];
        go += b_ih[3*HH + j] + b_hh[3*HH + j];
        float si = 1.f / (1.f + __expf(-gi));
        float so = 1.f / (1.f + __expf(-go));
        float c  = si * tanhf(gg);
        h[j] = so * tanhf(c);
    }
}

// ---------------- warp-per-row linear head ----------------
template<int N, int WPB, int UNR>
__global__ __launch_bounds__(WPB*32) void k_linw(const float* __restrict__ W,
                                                 const float* __restrict__ x,
                                                 const float* __restrict__ b,
                                                 float* __restrict__ out) {
    constexpr int R = N / 128;
    const int warp = threadIdx.x >> 5, lane = threadIdx.x & 31;
    const int row = blockIdx.x * WPB + warp;

    const float4* __restrict__ xv = (const float4*)x;
    const float4* __restrict__ wr = (const float4*)(W + (size_t)row * N);

    float acc = 0.f;
    #pragma unroll UNR
    for (int k = 0; k < R; k++) {
        int t = lane + 32*k;
        float4 v = xv[t];
        float4 w = wr[t];
        acc += w.x*v.x + w.y*v.y + w.z*v.z + w.w*v.w;
    }
    #pragma unroll
    for (int o = 16; o > 0; o >>= 1) acc += __shfl_xor_sync(0xffffffffu, acc, o);
    if (lane == 0) out[row] = acc + b[row];
}

// ---------------- final: inorm(512) -> leaky -> softmax(512), 3 blocks ----------------
__device__ __forceinline__ float blk_sum512(float v, volatile float* sh) {
    int t = threadIdx.x;
    #pragma unroll
    for (int o = 16; o > 0; o >>= 1) v += __shfl_xor_sync(0xffffffffu, v, o);
    if ((t & 31) == 0) sh[t >> 5] = v;
    __syncthreads();
    if (t == 0) {
        float a = 0.f;
        #pragma unroll
        for (int w = 0; w < 16; w++) a += sh[w];
        sh[16] = a;
    }
    __syncthreads();
    float r = sh[16];
    __syncthreads();
    return r;
}

__device__ __forceinline__ float blk_max512(float v, volatile float* sh) {
    int t = threadIdx.x;
    #pragma unroll
    for (int o = 16; o > 0; o >>= 1) v = fmaxf(v, __shfl_xor_sync(0xffffffffu, v, o));
    if ((t & 31) == 0) sh[t >> 5] = v;
    __syncthreads();
    if (t == 0) {
        float a = -3.4e38f;
        #pragma unroll
        for (int w = 0; w < 16; w++) a = fmaxf(a, sh[w]);
        sh[16] = a;
    }
    __syncthreads();
    float r = sh[16];
    __syncthreads();
    return r;
}

__global__ __launch_bounds__(512) void k_final(float* __restrict__ out) {
    __shared__ float sh[17];
    int b = blockIdx.x;   // 0..2
    int t = threadIdx.x;  // 0..511
    float v = g_o[b*SYM + t];
    float sum = blk_sum512(v, sh);
    float sq  = blk_sum512(v*v, sh);
    float m = sum * (1.0f/SYM);
    float var = sq * (1.0f/SYM) - m*m;
    float xn = (v - m) * rsqrtf(var + EPSF);
    xn = (xn >= 0.f) ? xn : 0.01f*xn;
    float mx = blk_max512(xn, sh);
    float e = expf(xn - mx);
    float se = blk_sum512(e, sh);
    out[b*SYM + t] = e / se;
}

// ---------------- launch ----------------
extern "C" void kernel_launch(void* const* d_in, const int* in_sizes, int n_in,
                              void* d_out, int out_size) {
    const float* wax   = (const float*)d_in[0];
    const float* blw   = (const float*)d_in[1];
    const float* blb   = (const float*)d_in[2];
    const float* w_ih0 = (const float*)d_in[3];
    // d_in[4] = w_hh0 (unused: h0 = 0)
    const float* b_ih0 = (const float*)d_in[5];
    const float* b_hh0 = (const float*)d_in[6];
    const float* w_ih1 = (const float*)d_in[7];
    const float* b_ih1 = (const float*)d_in[9];
    const float* b_hh1 = (const float*)d_in[10];
    const float* w_ih2 = (const float*)d_in[11];
    const float* b_ih2 = (const float*)d_in[13];
    const float* b_hh2 = (const float*)d_in[14];
    const float* lin_w = (const float*)d_in[15];
    const float* lin_b = (const float*)d_in[16];
    float* out = (float*)d_out;

    static float *p_v = nullptr, *p_ha = nullptr, *p_hb = nullptr, *p_o = nullptr;
    static cudaStream_t s1;
    static cudaEvent_t evFork, evJoin;
    static bool init = false;
    if (!init) {
        cudaGetSymbolAddress((void**)&p_v,  g_v);
        cudaGetSymbolAddress((void**)&p_ha, g_ha);
        cudaGetSymbolAddress((void**)&p_hb, g_hb);
        cudaGetSymbolAddress((void**)&p_o,  g_o);
        cudaStreamCreateWithFlags(&s1, cudaStreamNonBlocking);
        cudaEventCreateWithFlags(&evFork, cudaEventDisableTiming);
        cudaEventCreateWithFlags(&evJoin, cudaEventDisableTiming);
        init = true;
    }

    // ---- fork prefetch branch off the captured (legacy) stream ----
    cudaEventRecord(evFork, 0);
    cudaStreamWaitEvent(s1, evFork, 0);

    // Warm L2 with the weights of cells 1, 2 and the linear head (112 MB < 126 MB L2),
    // concurrent with cell0's DRAM stream. Pure cache-warm: no data dependencies.
    const unsigned GATE_LINES = (unsigned)((size_t)HH * HH * 4 / 128);     // 131072 per gate block
    k_pf<<<64, 256, 0, s1>>>(w_ih1 + (size_t)0*HH*HH, GATE_LINES);
    k_pf<<<64, 256, 0, s1>>>(w_ih1 + (size_t)2*HH*HH, GATE_LINES);
    k_pf<<<64, 256, 0, s1>>>(w_ih1 + (size_t)3*HH*HH, GATE_LINES);
    k_pf<<<64, 256, 0, s1>>>(w_ih2 + (size_t)0*HH*HH, GATE_LINES);
    k_pf<<<64, 256, 0, s1>>>(w_ih2 + (size_t)2*HH*HH, GATE_LINES);
    k_pf<<<64, 256, 0, s1>>>(w_ih2 + (size_t)3*HH*HH, GATE_LINES);
    k_pf<<<64, 256, 0, s1>>>(lin_w, (unsigned)((size_t)NO * HH * 4 / 128));
    cudaEventRecord(evJoin, s1);

    // ---- main dependency chain (unchanged from R7 best) ----
    k_front<<<SYM, 128>>>(wax, blw, blb);

    // cell 0: NT=192, MINB=8, ITER=18, grid 2048 (~6.2 TB/s measured)
    k_cell<192, 8, HIN, 1, true><<<HH, 192>>>(w_ih0, p_v, b_ih0, b_hh0, p_ha);

    // cells 1,2: NT=128, JPB=2, grid 1024 (best measured); weights should now be L2-hot
    k_cell<128, 8, HH, 2, true><<<HH/2, 128>>>(w_ih1, p_ha, b_ih1, b_hh1, p_hb);
    k_cell<128, 8, HH, 2, true><<<HH/2, 128>>>(w_ih2, p_hb, b_ih2, b_hh2, p_ha);

    // linear head
    k_linw<HH, 4, 8><<<NO/4, 128>>>(lin_w, p_ha, lin_b, p_o);

    // join prefetch branch back into the captured stream before the last kernel
    cudaStreamWaitEvent(0, evJoin, 0);
    k_final<<<NS, 512>>>(out);
}

// round 9
// speedup vs baseline: 1.1200x; 1.1200x over previous
#include <cuda_runtime.h>
#include <math.h>

#define NS 3
#define SYM 512
#define FD 20
#define NLIN 11
#define NOUT 9
#define HH 2048
#define HIN (NS*SYM*NOUT)   /* 13824 */
#define NO (NS*SYM)         /* 1536 */
#define EPSF 1e-9f

#define FG  1024            /* fused kernel grid (all-resident: < 8*148) */
#define FNT 128             /* fused kernel block size */

// ---------------- device scratch (no allocations allowed) ----------------
__device__ float g_v[HIN];
__device__ float g_ha[HH];
__device__ float g_hb[HH];
__device__ float g_hc[HH];
__device__ float g_o[NO];
__device__ unsigned g_cnt = 0;
__device__ unsigned g_gen = 0;

// ---------------- front end: inorm -> DFT -> bilinear -> leaky -> softmax(NS) ----------------
__global__ __launch_bounds__(128) void k_front(const float* __restrict__ wax,
                                               const float* __restrict__ blw,
                                               const float* __restrict__ blb) {
    int s = blockIdx.x;           // 0..511
    int tid = threadIdx.x;
    int warp = tid >> 5, lane = tid & 31;

    __shared__ float sh_xn[NS][FD];
    __shared__ float sh_re[NS][NLIN], sh_im[NS][NLIN];
    __shared__ float sh_z[NS][NOUT];

    if (warp < NS) {
        int b = warp;
        float x = 0.f;
        if (lane < FD) x = wax[(b*SYM + s)*FD + lane];
        float sum = x, sq = x*x;
        #pragma unroll
        for (int o = 16; o > 0; o >>= 1) {
            sum += __shfl_xor_sync(0xffffffffu, sum, o);
            sq  += __shfl_xor_sync(0xffffffffu, sq,  o);
        }
        float m = sum * (1.0f/FD);
        float var = sq * (1.0f/FD) - m*m;
        float r = rsqrtf(var + EPSF);
        if (lane < FD) sh_xn[b][lane] = (x - m) * r;
        __syncwarp();

        if (lane < NLIN) {
            float re = 0.f, im = 0.f;
            #pragma unroll
            for (int f = 0; f < FD; f++) {
                float sn, cs;
                sincospif((float)(lane*f) * 0.1f, &sn, &cs);
                float xv = sh_xn[b][f];
                re += xv * cs;
                im -= xv * sn;
            }
            sh_re[b][lane] = re;
            sh_im[b][lane] = im;
        }
        __syncwarp();

        if (lane < NOUT) {
            int k = lane;
            float z = blb[k];
            #pragma unroll
            for (int i = 0; i < NLIN; i++) {
                float t = 0.f;
                #pragma unroll
                for (int j = 0; j < NLIN; j++)
                    t += blw[(k*NLIN + i)*NLIN + j] * sh_im[b][j];
                z += sh_re[b][i] * t;
            }
            z = (z >= 0.f) ? z : 0.01f*z;
            sh_z[b][k] = z;
        }
    }
    __syncthreads();

    if (tid < NOUT) {
        int k = tid;
        float z0 = sh_z[0][k], z1 = sh_z[1][k], z2 = sh_z[2][k];
        float m = fmaxf(z0, fmaxf(z1, z2));
        float e0 = expf(z0-m), e1 = expf(z1-m), e2 = expf(z2-m);
        float inv = 1.f/(e0+e1+e2);
        g_v[s*(NS*NOUT) + 0*NOUT + k] = e0*inv;
        g_v[s*(NS*NOUT) + 1*NOUT + k] = e1*inv;
        g_v[s*(NS*NOUT) + 2*NOUT + k] = e2*inv;
    }
}

// ---------------- cell0: proven plain-LDG streaming (NT=192, MINB=8) ----------------
template<int NT, int MINB, int N, int JPB, bool STREAM>
__global__ __launch_bounds__(NT, MINB) void k_cell(const float* __restrict__ W,
                                                   const float* __restrict__ x,
                                                   const float* __restrict__ b_ih,
                                                   const float* __restrict__ b_hh,
                                                   float* __restrict__ h) {
    constexpr int N4   = N / 4;
    constexpr int ITER = N4 / NT;
    constexpr int NR   = 3 * JPB;
    const int j0 = blockIdx.x * JPB;
    const int tid = threadIdx.x;

    const float4* __restrict__ xv = (const float4*)x;
    const float4* Wr[NR];
    #pragma unroll
    for (int q = 0; q < JPB; q++) {
        int j = j0 + q;
        Wr[3*q + 0] = (const float4*)(W + (size_t)(0*HH + j) * N);
        Wr[3*q + 1] = (const float4*)(W + (size_t)(2*HH + j) * N);
        Wr[3*q + 2] = (const float4*)(W + (size_t)(3*HH + j) * N);
    }

    float acc[NR];
    #pragma unroll
    for (int r = 0; r < NR; r++) acc[r] = 0.f;

    #pragma unroll 6
    for (int it = 0; it < ITER; it++) {
        int t = tid + it * NT;
        float4 v = xv[t];
        #pragma unroll
        for (int r = 0; r < NR; r++) {
            float4 w = STREAM ? __ldcs(&Wr[r][t]) : Wr[r][t];
            acc[r] += w.x*v.x + w.y*v.y + w.z*v.z + w.w*v.w;
        }
    }

    __shared__ float sred[NR][NT/32];
    #pragma unroll
    for (int r = 0; r < NR; r++) {
        float a = acc[r];
        #pragma unroll
        for (int o = 16; o > 0; o >>= 1) a += __shfl_xor_sync(0xffffffffu, a, o);
        if ((tid & 31) == 0) sred[r][tid >> 5] = a;
    }
    __syncthreads();

    if (tid < JPB) {
        int q = tid, j = j0 + q;
        float gi = 0.f, gg = 0.f, go = 0.f;
        #pragma unroll
        for (int w = 0; w < NT/32; w++) {
            gi += sred[3*q + 0][w];
            gg += sred[3*q + 1][w];
            go += sred[3*q + 2][w];
        }
        gi += b_ih[j]        + b_hh[j];
        gg += b_ih[2*HH + j] + b_hh[2*HH + j];
        go += b_ih[3*HH + j] + b_hh[3*HH + j];
        float si = 1.f / (1.f + __expf(-gi));
        float so = 1.f / (1.f + __expf(-go));
        float c  = si * tanhf(gg);
        h[j] = so * tanhf(c);
    }
}

// ---------------- fused persistent kernel: cell1 -> cell2 -> lin -> final ----------------
__device__ __forceinline__ void gridbar() {
    __threadfence();
    __syncthreads();
    if (threadIdx.x == 0) {
        unsigned gen = atomicAdd(&g_gen, 0u);
        if (atomicAdd(&g_cnt, 1u) == FG - 1u) {
            g_cnt = 0u;
            __threadfence();
            atomicAdd(&g_gen, 1u);
        } else {
            while (atomicAdd(&g_gen, 0u) == gen) { __nanosleep(32); }
        }
    }
    __syncthreads();
}

__device__ __forceinline__ void pf_l2(const float* p) {
    asm volatile("prefetch.global.L2 [%0];" :: "l"(p));
}

// One H->H LSTM cell phase (JPB=2, proven config), with optional L2 prefetch of
// the NEXT phase's weights folded into the main loop (targets idle DRAM).
__device__ __forceinline__ void cell_phase(const float* __restrict__ W,
                                           const float* __restrict__ x,
                                           const float* __restrict__ b_ih,
                                           const float* __restrict__ b_hh,
                                           float* __restrict__ h,
                                           const float* pf0, const float* pf1,
                                           const float* pf2, unsigned pfn,
                                           float sred[6][FNT/32]) {
    constexpr int ITER = (HH/4) / FNT;   // 4
    const int tid = threadIdx.x;
    const int j0 = blockIdx.x * 2;
    const unsigned gid = blockIdx.x * FNT + tid;

    const float4* __restrict__ xv = (const float4*)x;
    const float4* Wr[6];
    #pragma unroll
    for (int q = 0; q < 2; q++) {
        int j = j0 + q;
        Wr[3*q + 0] = (const float4*)(W + (size_t)(0*HH + j) * HH);
        Wr[3*q + 1] = (const float4*)(W + (size_t)(2*HH + j) * HH);
        Wr[3*q + 2] = (const float4*)(W + (size_t)(3*HH + j) * HH);
    }

    float acc[6];
    #pragma unroll
    for (int r = 0; r < 6; r++) acc[r] = 0.f;

    #pragma unroll
    for (int it = 0; it < ITER; it++) {
        // one prefetch line per thread per region, spread over iterations
        if (it == 0 && pf0 && gid < pfn) pf_l2(pf0 + (size_t)gid * 32);
        if (it == 1 && pf1 && gid < pfn) pf_l2(pf1 + (size_t)gid * 32);
        if (it == 2 && pf2 && gid < pfn) pf_l2(pf2 + (size_t)gid * 32);

        int t = tid + it * FNT;
        float4 v = xv[t];
        #pragma unroll
        for (int r = 0; r < 6; r++) {
            float4 w = __ldcs(&Wr[r][t]);
            acc[r] += w.x*v.x + w.y*v.y + w.z*v.z + w.w*v.w;
        }
    }

    #pragma unroll
    for (int r = 0; r < 6; r++) {
        float a = acc[r];
        #pragma unroll
        for (int o = 16; o > 0; o >>= 1) a += __shfl_xor_sync(0xffffffffu, a, o);
        if ((tid & 31) == 0) sred[r][tid >> 5] = a;
    }
    __syncthreads();

    if (tid < 2) {
        int q = tid, j = j0 + q;
        float gi = 0.f, gg = 0.f, go = 0.f;
        #pragma unroll
        for (int w = 0; w < FNT/32; w++) {
            gi += sred[3*q + 0][w];
            gg += sred[3*q + 1][w];
            go += sred[3*q + 2][w];
        }
        gi += b_ih[j]        + b_hh[j];
        gg += b_ih[2*HH + j] + b_hh[2*HH + j];
        go += b_ih[3*HH + j] + b_hh[3*HH + j];
        float si = 1.f / (1.f + __expf(-gi));
        float so = 1.f / (1.f + __expf(-go));
        float c  = si * tanhf(gg);
        h[j] = so * tanhf(c);
    }
    __syncthreads();
}

__device__ __forceinline__ float bsum128(float v, volatile float* sh) {
    int t = threadIdx.x;
    #pragma unroll
    for (int o = 16; o > 0; o >>= 1) v += __shfl_xor_sync(0xffffffffu, v, o);
    if ((t & 31) == 0) sh[t >> 5] = v;
    __syncthreads();
    float r = sh[0] + sh[1] + sh[2] + sh[3];
    __syncthreads();
    return r;
}
__device__ __forceinline__ float bmax128(float v, volatile float* sh) {
    int t = threadIdx.x;
    #pragma unroll
    for (int o = 16; o > 0; o >>= 1) v = fmaxf(v, __shfl_xor_sync(0xffffffffu, v, o));
    if ((t & 31) == 0) sh[t >> 5] = v;
    __syncthreads();
    float r = fmaxf(fmaxf(sh[0], sh[1]), fmaxf(sh[2], sh[3]));
    __syncthreads();
    return r;
}

__global__ __launch_bounds__(FNT, 8) void k_fused(const float* __restrict__ w_ih1,
                                                  const float* __restrict__ b_ih1,
                                                  const float* __restrict__ b_hh1,
                                                  const float* __restrict__ w_ih2,
                                                  const float* __restrict__ b_ih2,
                                                  const float* __restrict__ b_hh2,
                                                  const float* __restrict__ lin_w,
                                                  const float* __restrict__ lin_b,
                                                  float* __restrict__ out) {
    __shared__ float sred[6][FNT/32];
    const int tid = threadIdx.x;

    // phase 1: cell1 (g_ha -> g_hb), prefetch w_ih2 gate regions (i, g, o)
    cell_phase(w_ih1, g_ha, b_ih1, b_hh1, g_hb,
               w_ih2 + (size_t)0*HH*HH,
               w_ih2 + (size_t)2*HH*HH,
               w_ih2 + (size_t)3*HH*HH,
               (unsigned)((size_t)HH*HH*4/128),      // 131072 lines per region
               sred);
    gridbar();

    // phase 2: cell2 (g_hb -> g_hc), prefetch lin_w
    cell_phase(w_ih2, g_hb, b_ih2, b_hh2, g_hc,
               lin_w, (const float*)0, (const float*)0,
               (unsigned)((size_t)NO*HH*4/128),      // 98304 lines
               sred);
    gridbar();

    // phase 3: linear head, warp-per-row (blocks 0..383, 4 rows each)
    if (blockIdx.x < NO/4) {
        int warp = tid >> 5, lane = tid & 31;
        int row = blockIdx.x * 4 + warp;
        const float4* __restrict__ xv = (const float4*)g_hc;
        const float4* __restrict__ wr = (const float4*)(lin_w + (size_t)row * HH);
        float acc = 0.f;
        #pragma unroll
        for (int k = 0; k < 16; k++) {
            int t = lane + 32*k;
            float4 v = xv[t];
            float4 w = __ldcs(wr + t);
            acc += w.x*v.x + w.y*v.y + w.z*v.z + w.w*v.w;
        }
        #pragma unroll
        for (int o = 16; o > 0; o >>= 1) acc += __shfl_xor_sync(0xffffffffu, acc, o);
        if (lane == 0) g_o[row] = acc + lin_b[row];
    }
    gridbar();

    // phase 4: inorm(512) -> leaky -> softmax(512), blocks 0..2 (4 elems/thread)
    if (blockIdx.x < NS) {
        volatile float* sh = (volatile float*)&sred[0][0];
        int b = blockIdx.x;
        float v[4];
        #pragma unroll
        for (int q = 0; q < 4; q++) v[q] = g_o[b*SYM + tid + q*128];

        float s  = bsum128(v[0] + v[1] + v[2] + v[3], sh);
        float sq = bsum128(v[0]*v[0] + v[1]*v[1] + v[2]*v[2] + v[3]*v[3], sh);
        float m = s * (1.0f/SYM);
        float var = sq * (1.0f/SYM) - m*m;
        float r = rsqrtf(var + EPSF);

        float xn[4], mloc = -3.4e38f;
        #pragma unroll
        for (int q = 0; q < 4; q++) {
            float t = (v[q] - m) * r;
            t = (t >= 0.f) ? t : 0.01f*t;
            xn[q] = t;
            mloc = fmaxf(mloc, t);
        }
        float mx = bmax128(mloc, sh);
        float e[4];
        #pragma unroll
        for (int q = 0; q < 4; q++) e[q] = expf(xn[q] - mx);
        float se = bsum128(e[0] + e[1] + e[2] + e[3], sh);
        float inv = 1.f / se;
        #pragma unroll
        for (int q = 0; q < 4; q++) out[b*SYM + tid + q*128] = e[q] * inv;
    }
}

// ---------------- launch ----------------
extern "C" void kernel_launch(void* const* d_in, const int* in_sizes, int n_in,
                              void* d_out, int out_size) {
    const float* wax   = (const float*)d_in[0];
    const float* blw   = (const float*)d_in[1];
    const float* blb   = (const float*)d_in[2];
    const float* w_ih0 = (const float*)d_in[3];
    // d_in[4] = w_hh0 (unused: h0 = 0)
    const float* b_ih0 = (const float*)d_in[5];
    const float* b_hh0 = (const float*)d_in[6];
    const float* w_ih1 = (const float*)d_in[7];
    const float* b_ih1 = (const float*)d_in[9];
    const float* b_hh1 = (const float*)d_in[10];
    const float* w_ih2 = (const float*)d_in[11];
    const float* b_ih2 = (const float*)d_in[13];
    const float* b_hh2 = (const float*)d_in[14];
    const float* lin_w = (const float*)d_in[15];
    const float* lin_b = (const float*)d_in[16];
    float* out = (float*)d_out;

    static float *p_v = nullptr, *p_ha = nullptr;
    if (!p_v) {
        cudaGetSymbolAddress((void**)&p_v,  g_v);
        cudaGetSymbolAddress((void**)&p_ha, g_ha);
    }

    k_front<<<SYM, 128>>>(wax, blw, blb);

    // cell 0: proven best config (NT=192, MINB=8, ITER=18, grid 2048, ~6.2 TB/s)
    k_cell<192, 8, HIN, 1, true><<<HH, 192>>>(w_ih0, p_v, b_ih0, b_hh0, p_ha);

    // cells 1,2 + linear head + finalize: one persistent kernel, 3 grid barriers,
    // next-phase weights prefetched into the latency-bound phases' idle DRAM.
    k_fused<<<FG, FNT>>>(w_ih1, b_ih1, b_hh1,
                         w_ih2, b_ih2, b_hh2,
                         lin_w, lin_b, out);
}

// round 10
// speedup vs baseline: 1.1377x; 1.0159x over previous
#include <cuda_runtime.h>
#include <math.h>

#define NS 3
#define SYM 512
#define FD 20
#define NLIN 11
#define NOUT 9
#define HH 2048
#define HIN (NS*SYM*NOUT)   /* 13824 */
#define NO (NS*SYM)         /* 1536 */
#define EPSF 1e-9f

// ---------------- device scratch (no allocations allowed) ----------------
__device__ float g_v[HIN];
__device__ float g_ha[HH];
__device__ float g_hb[HH];
__device__ float g_o[NO];

// DFT twiddles: cos/sin(pi*m/10), m = 0..19 (exact fp32 literals)
__constant__ float c_cs[20] = {
     1.0f,            0.9510565163f,  0.8090169944f,  0.5877852523f,  0.3090169944f,
     0.0f,           -0.3090169944f, -0.5877852523f, -0.8090169944f, -0.9510565163f,
    -1.0f,           -0.9510565163f, -0.8090169944f, -0.5877852523f, -0.3090169944f,
     0.0f,            0.3090169944f,  0.5877852523f,  0.8090169944f,  0.9510565163f
};
__constant__ float c_sn[20] = {
     0.0f,            0.3090169944f,  0.5877852523f,  0.8090169944f,  0.9510565163f,
     1.0f,            0.9510565163f,  0.8090169944f,  0.5877852523f,  0.3090169944f,
     0.0f,           -0.3090169944f, -0.5877852523f, -0.8090169944f, -0.9510565163f,
    -1.0f,           -0.9510565163f, -0.8090169944f, -0.5877852523f, -0.3090169944f
};

// ---------------- front end: inorm -> DFT (table twiddles) -> bilinear -> leaky -> softmax(NS) ----------------
__global__ __launch_bounds__(128) void k_front(const float* __restrict__ wax,
                                               const float* __restrict__ blw,
                                               const float* __restrict__ blb) {
    int s = blockIdx.x;           // 0..511
    int tid = threadIdx.x;
    int warp = tid >> 5, lane = tid & 31;

    __shared__ float sh_xn[NS][FD];
    __shared__ float sh_re[NS][NLIN], sh_im[NS][NLIN];
    __shared__ float sh_z[NS][NOUT];

    if (warp < NS) {
        int b = warp;
        float x = 0.f;
        if (lane < FD) x = wax[(b*SYM + s)*FD + lane];
        float sum = x, sq = x*x;
        #pragma unroll
        for (int o = 16; o > 0; o >>= 1) {
            sum += __shfl_xor_sync(0xffffffffu, sum, o);
            sq  += __shfl_xor_sync(0xffffffffu, sq,  o);
        }
        float m = sum * (1.0f/FD);
        float var = sq * (1.0f/FD) - m*m;
        float r = rsqrtf(var + EPSF);
        if (lane < FD) sh_xn[b][lane] = (x - m) * r;
        __syncwarp();

        if (lane < NLIN) {
            float re = 0.f, im = 0.f;
            int idx = 0;                       // (lane*f) mod 20, tracked incrementally
            #pragma unroll
            for (int f = 0; f < FD; f++) {
                float xv = sh_xn[b][f];
                re += xv * c_cs[idx];
                im -= xv * c_sn[idx];
                idx += lane;
                if (idx >= FD) idx -= FD;      // lane < 20, so one subtract suffices
            }
            sh_re[b][lane] = re;
            sh_im[b][lane] = im;
        }
        __syncwarp();

        if (lane < NOUT) {
            int k = lane;
            float z = blb[k];
            #pragma unroll
            for (int i = 0; i < NLIN; i++) {
                float t = 0.f;
                #pragma unroll
                for (int j = 0; j < NLIN; j++)
                    t += blw[(k*NLIN + i)*NLIN + j] * sh_im[b][j];
                z += sh_re[b][i] * t;
            }
            z = (z >= 0.f) ? z : 0.01f*z;   // leaky_relu
            sh_z[b][k] = z;
        }
    }
    __syncthreads();

    if (tid < NOUT) {
        int k = tid;
        float z0 = sh_z[0][k], z1 = sh_z[1][k], z2 = sh_z[2][k];
        float m = fmaxf(z0, fmaxf(z1, z2));
        float e0 = expf(z0-m), e1 = expf(z1-m), e2 = expf(z2-m);
        float inv = 1.f/(e0+e1+e2);
        g_v[s*(NS*NOUT) + 0*NOUT + k] = e0*inv;
        g_v[s*(NS*NOUT) + 1*NOUT + k] = e1*inv;
        g_v[s*(NS*NOUT) + 2*NOUT + k] = e2*inv;
    }
}

// ---------------- fused LSTM cell (zero state): block computes i,g,o rows of JPB j's ----------------
template<int NT, int MINB, int N, int JPB, bool STREAM>
__global__ __launch_bounds__(NT, MINB) void k_cell(const float* __restrict__ W,
                                                   const float* __restrict__ x,
                                                   const float* __restrict__ b_ih,
                                                   const float* __restrict__ b_hh,
                                                   float* __restrict__ h) {
    constexpr int N4   = N / 4;
    constexpr int ITER = N4 / NT;       // exact by construction
    constexpr int NR   = 3 * JPB;
    const int j0 = blockIdx.x * JPB;
    const int tid = threadIdx.x;

    const float4* __restrict__ xv = (const float4*)x;
    const float4* Wr[NR];
    #pragma unroll
    for (int q = 0; q < JPB; q++) {
        int j = j0 + q;
        Wr[3*q + 0] = (const float4*)(W + (size_t)(0*HH + j) * N);  // i
        Wr[3*q + 1] = (const float4*)(W + (size_t)(2*HH + j) * N);  // g
        Wr[3*q + 2] = (const float4*)(W + (size_t)(3*HH + j) * N);  // o
    }

    float acc[NR];
    #pragma unroll
    for (int r = 0; r < NR; r++) acc[r] = 0.f;

    #pragma unroll 6
    for (int it = 0; it < ITER; it++) {
        int t = tid + it * NT;
        float4 v = xv[t];
        #pragma unroll
        for (int r = 0; r < NR; r++) {
            float4 w = STREAM ? __ldcs(&Wr[r][t]) : Wr[r][t];
            acc[r] += w.x*v.x + w.y*v.y + w.z*v.z + w.w*v.w;
        }
    }

    __shared__ float sred[NR][NT/32];
    #pragma unroll
    for (int r = 0; r < NR; r++) {
        float a = acc[r];
        #pragma unroll
        for (int o = 16; o > 0; o >>= 1) a += __shfl_xor_sync(0xffffffffu, a, o);
        if ((tid & 31) == 0) sred[r][tid >> 5] = a;
    }
    __syncthreads();

    if (tid < JPB) {
        int q = tid, j = j0 + q;
        float gi = 0.f, gg = 0.f, go = 0.f;
        #pragma unroll
        for (int w = 0; w < NT/32; w++) {
            gi += sred[3*q + 0][w];
            gg += sred[3*q + 1][w];
            go += sred[3*q + 2][w];
        }
        gi += b_ih[j]        + b_hh[j];
        gg += b_ih[2*HH + j] + b_hh[2*HH + j];
        go += b_ih[3*HH + j] + b_hh[3*HH + j];
        float si = 1.f / (1.f + __expf(-gi));
        float so = 1.f / (1.f + __expf(-go));
        float c  = si * tanhf(gg);
        h[j] = so * tanhf(c);
    }
}

// ---------------- warp-per-row linear head ----------------
template<int N, int WPB, int UNR>
__global__ __launch_bounds__(WPB*32) void k_linw(const float* __restrict__ W,
                                                 const float* __restrict__ x,
                                                 const float* __restrict__ b,
                                                 float* __restrict__ out) {
    constexpr int R = N / 128;
    const int warp = threadIdx.x >> 5, lane = threadIdx.x & 31;
    const int row = blockIdx.x * WPB + warp;

    const float4* __restrict__ xv = (const float4*)x;
    const float4* __restrict__ wr = (const float4*)(W + (size_t)row * N);

    float acc = 0.f;
    #pragma unroll UNR
    for (int k = 0; k < R; k++) {
        int t = lane + 32*k;
        float4 v = xv[t];
        float4 w = __ldcs(wr + t);
        acc += w.x*v.x + w.y*v.y + w.z*v.z + w.w*v.w;
    }
    #pragma unroll
    for (int o = 16; o > 0; o >>= 1) acc += __shfl_xor_sync(0xffffffffu, acc, o);
    if (lane == 0) out[row] = acc + b[row];
}

// ---------------- final: inorm(512) -> leaky -> softmax(512), 3 blocks ----------------
__device__ __forceinline__ float blk_sum512(float v, volatile float* sh) {
    int t = threadIdx.x;
    #pragma unroll
    for (int o = 16; o > 0; o >>= 1) v += __shfl_xor_sync(0xffffffffu, v, o);
    if ((t & 31) == 0) sh[t >> 5] = v;
    __syncthreads();
    if (t == 0) {
        float a = 0.f;
        #pragma unroll
        for (int w = 0; w < 16; w++) a += sh[w];
        sh[16] = a;
    }
    __syncthreads();
    float r = sh[16];
    __syncthreads();
    return r;
}

__device__ __forceinline__ float blk_max512(float v, volatile float* sh) {
    int t = threadIdx.x;
    #pragma unroll
    for (int o = 16; o > 0; o >>= 1) v = fmaxf(v, __shfl_xor_sync(0xffffffffu, v, o));
    if ((t & 31) == 0) sh[t >> 5] = v;
    __syncthreads();
    if (t == 0) {
        float a = -3.4e38f;
        #pragma unroll
        for (int w = 0; w < 16; w++) a = fmaxf(a, sh[w]);
        sh[16] = a;
    }
    __syncthreads();
    float r = sh[16];
    __syncthreads();
    return r;
}

__global__ __launch_bounds__(512) void k_final(float* __restrict__ out) {
    __shared__ float sh[17];
    int b = blockIdx.x;   // 0..2
    int t = threadIdx.x;  // 0..511
    float v = g_o[b*SYM + t];
    float sum = blk_sum512(v, sh);
    float sq  = blk_sum512(v*v, sh);
    float m = sum * (1.0f/SYM);
    float var = sq * (1.0f/SYM) - m*m;
    float xn = (v - m) * rsqrtf(var + EPSF);
    xn = (xn >= 0.f) ? xn : 0.01f*xn;
    float mx = blk_max512(xn, sh);
    float e = expf(xn - mx);
    float se = blk_sum512(e, sh);
    out[b*SYM + t] = e / se;
}

// ---------------- launch ----------------
extern "C" void kernel_launch(void* const* d_in, const int* in_sizes, int n_in,
                              void* d_out, int out_size) {
    const float* wax   = (const float*)d_in[0];
    const float* blw   = (const float*)d_in[1];
    const float* blb   = (const float*)d_in[2];
    const float* w_ih0 = (const float*)d_in[3];
    // d_in[4] = w_hh0 (unused: h0 = 0)
    const float* b_ih0 = (const float*)d_in[5];
    const float* b_hh0 = (const float*)d_in[6];
    const float* w_ih1 = (const float*)d_in[7];
    const float* b_ih1 = (const float*)d_in[9];
    const float* b_hh1 = (const float*)d_in[10];
    const float* w_ih2 = (const float*)d_in[11];
    const float* b_ih2 = (const float*)d_in[13];
    const float* b_hh2 = (const float*)d_in[14];
    const float* lin_w = (const float*)d_in[15];
    const float* lin_b = (const float*)d_in[16];
    float* out = (float*)d_out;

    static float *p_v = nullptr, *p_ha = nullptr, *p_hb = nullptr, *p_o = nullptr;
    if (!p_v) {
        cudaGetSymbolAddress((void**)&p_v,  g_v);
        cudaGetSymbolAddress((void**)&p_ha, g_ha);
        cudaGetSymbolAddress((void**)&p_hb, g_hb);
        cudaGetSymbolAddress((void**)&p_o,  g_o);
    }

    k_front<<<SYM, 128>>>(wax, blw, blb);

    // cell 0: best measured config (NT=192, MINB=8, ITER=18, grid 2048, ~6.2 TB/s)
    k_cell<192, 8, HIN, 1, true><<<HH, 192>>>(w_ih0, p_v, b_ih0, b_hh0, p_ha);

    // cells 1,2: best measured config (NT=128, JPB=2, grid 1024)
    k_cell<128, 8, HH, 2, true><<<HH/2, 128>>>(w_ih1, p_ha, b_ih1, b_hh1, p_hb);
    k_cell<128, 8, HH, 2, true><<<HH/2, 128>>>(w_ih2, p_hb, b_ih2, b_hh2, p_ha);

    // linear head: warp-per-row, 4 warps/block, grid 384.
    k_linw<HH, 4, 8><<<NO/4, 128>>>(lin_w, p_ha, lin_b, p_o);

    k_final<<<NS, 512>>>(out);
}

// round 11
// speedup vs baseline: 1.1640x; 1.0231x over previous
#include <cuda_runtime.h>
#include <math.h>

#define NS 3
#define SYM 512
#define FD 20
#define NLIN 11
#define NOUT 9
#define HH 2048
#define HIN (NS*SYM*NOUT)   /* 13824 */
#define NO (NS*SYM)         /* 1536 */
#define EPSF 1e-9f

// ---------------- device scratch (no allocations allowed) ----------------
__device__ float g_v[HIN];
__device__ float g_ha[HH];
__device__ float g_hb[HH];
__device__ float g_o[NO];

// DFT twiddles: cos/sin(pi*m/10), m = 0..19 (exact fp32 literals)
__constant__ float c_cs[20] = {
     1.0f,            0.9510565163f,  0.8090169944f,  0.5877852523f,  0.3090169944f,
     0.0f,           -0.3090169944f, -0.5877852523f, -0.8090169944f, -0.9510565163f,
    -1.0f,           -0.9510565163f, -0.8090169944f, -0.5877852523f, -0.3090169944f,
     0.0f,            0.3090169944f,  0.5877852523f,  0.8090169944f,  0.9510565163f
};
__constant__ float c_sn[20] = {
     0.0f,            0.3090169944f,  0.5877852523f,  0.8090169944f,  0.9510565163f,
     1.0f,            0.9510565163f,  0.8090169944f,  0.5877852523f,  0.3090169944f,
     0.0f,           -0.3090169944f, -0.5877852523f, -0.8090169944f, -0.9510565163f,
    -1.0f,           -0.9510565163f, -0.8090169944f, -0.5877852523f, -0.3090169944f
};

// ---------------- front end: inorm -> DFT (table twiddles) -> bilinear -> leaky -> softmax(NS) ----------------
__global__ __launch_bounds__(128) void k_front(const float* __restrict__ wax,
                                               const float* __restrict__ blw,
                                               const float* __restrict__ blb) {
    int s = blockIdx.x;           // 0..511
    int tid = threadIdx.x;
    int warp = tid >> 5, lane = tid & 31;

    __shared__ float sh_xn[NS][FD];
    __shared__ float sh_re[NS][NLIN], sh_im[NS][NLIN];
    __shared__ float sh_z[NS][NOUT];

    if (warp < NS) {
        int b = warp;
        float x = 0.f;
        if (lane < FD) x = wax[(b*SYM + s)*FD + lane];
        float sum = x, sq = x*x;
        #pragma unroll
        for (int o = 16; o > 0; o >>= 1) {
            sum += __shfl_xor_sync(0xffffffffu, sum, o);
            sq  += __shfl_xor_sync(0xffffffffu, sq,  o);
        }
        float m = sum * (1.0f/FD);
        float var = sq * (1.0f/FD) - m*m;
        float r = rsqrtf(var + EPSF);
        if (lane < FD) sh_xn[b][lane] = (x - m) * r;
        __syncwarp();

        if (lane < NLIN) {
            float re = 0.f, im = 0.f;
            int idx = 0;                       // (lane*f) mod 20, tracked incrementally
            #pragma unroll
            for (int f = 0; f < FD; f++) {
                float xv = sh_xn[b][f];
                re += xv * c_cs[idx];
                im -= xv * c_sn[idx];
                idx += lane;
                if (idx >= FD) idx -= FD;
            }
            sh_re[b][lane] = re;
            sh_im[b][lane] = im;
        }
        __syncwarp();

        if (lane < NOUT) {
            int k = lane;
            float z = blb[k];
            #pragma unroll
            for (int i = 0; i < NLIN; i++) {
                float t = 0.f;
                #pragma unroll
                for (int j = 0; j < NLIN; j++)
                    t += blw[(k*NLIN + i)*NLIN + j] * sh_im[b][j];
                z += sh_re[b][i] * t;
            }
            z = (z >= 0.f) ? z : 0.01f*z;   // leaky_relu
            sh_z[b][k] = z;
        }
    }
    __syncthreads();

    if (tid < NOUT) {
        int k = tid;
        float z0 = sh_z[0][k], z1 = sh_z[1][k], z2 = sh_z[2][k];
        float m = fmaxf(z0, fmaxf(z1, z2));
        float e0 = expf(z0-m), e1 = expf(z1-m), e2 = expf(z2-m);
        float inv = 1.f/(e0+e1+e2);
        g_v[s*(NS*NOUT) + 0*NOUT + k] = e0*inv;
        g_v[s*(NS*NOUT) + 1*NOUT + k] = e1*inv;
        g_v[s*(NS*NOUT) + 2*NOUT + k] = e2*inv;
    }
}

__device__ __forceinline__ void pf_l2(const float* p) {
    asm volatile("prefetch.global.L2 [%0];" :: "l"(p));
}

// ---------------- fused LSTM cell (zero state): block computes i,g,o rows of JPB j's ----------------
// PF: fold bounded L2 prefetch of the NEXT consumer's weights into the stream
// (only for the latency-bound H->H cells; cell0 keeps identical codegen with PF=false).
template<int NT, int MINB, int N, int JPB, bool STREAM, bool PF>
__global__ __launch_bounds__(NT, MINB) void k_cell(const float* __restrict__ W,
                                                   const float* __restrict__ x,
                                                   const float* __restrict__ b_ih,
                                                   const float* __restrict__ b_hh,
                                                   float* __restrict__ h,
                                                   const float* __restrict__ pfA,
                                                   unsigned pfAn,
                                                   const float* __restrict__ pfB,
                                                   unsigned pfBn) {
    constexpr int N4   = N / 4;
    constexpr int ITER = N4 / NT;       // exact by construction
    constexpr int NR   = 3 * JPB;
    const int j0 = blockIdx.x * JPB;
    const int tid = threadIdx.x;
    const unsigned gid = blockIdx.x * NT + tid;

    const float4* __restrict__ xv = (const float4*)x;
    const float4* Wr[NR];
    #pragma unroll
    for (int q = 0; q < JPB; q++) {
        int j = j0 + q;
        Wr[3*q + 0] = (const float4*)(W + (size_t)(0*HH + j) * N);  // i
        Wr[3*q + 1] = (const float4*)(W + (size_t)(2*HH + j) * N);  // g
        Wr[3*q + 2] = (const float4*)(W + (size_t)(3*HH + j) * N);  // o
    }

    float acc[NR];
    #pragma unroll
    for (int r = 0; r < NR; r++) acc[r] = 0.f;

    #pragma unroll 6
    for (int it = 0; it < ITER; it++) {
        if (PF) {   // one 128B line per thread on selected iterations (bounded, fire-and-forget)
            if (it == 0 && pfA && gid < pfAn) pf_l2(pfA + (size_t)gid * 32);
            if (it == 1 && pfB && gid < pfBn) pf_l2(pfB + (size_t)gid * 32);
        }
        int t = tid + it * NT;
        float4 v = xv[t];
        #pragma unroll
        for (int r = 0; r < NR; r++) {
            float4 w = STREAM ? __ldcs(&Wr[r][t]) : Wr[r][t];
            acc[r] += w.x*v.x + w.y*v.y + w.z*v.z + w.w*v.w;
        }
    }

    __shared__ float sred[NR][NT/32];
    #pragma unroll
    for (int r = 0; r < NR; r++) {
        float a = acc[r];
        #pragma unroll
        for (int o = 16; o > 0; o >>= 1) a += __shfl_xor_sync(0xffffffffu, a, o);
        if ((tid & 31) == 0) sred[r][tid >> 5] = a;
    }
    __syncthreads();

    if (tid < JPB) {
        int q = tid, j = j0 + q;
        float gi = 0.f, gg = 0.f, go = 0.f;
        #pragma unroll
        for (int w = 0; w < NT/32; w++) {
            gi += sred[3*q + 0][w];
            gg += sred[3*q + 1][w];
            go += sred[3*q + 2][w];
        }
        gi += b_ih[j]        + b_hh[j];
        gg += b_ih[2*HH + j] + b_hh[2*HH + j];
        go += b_ih[3*HH + j] + b_hh[3*HH + j];
        float si = 1.f / (1.f + __expf(-gi));
        float so = 1.f / (1.f + __expf(-go));
        float c  = si * tanhf(gg);
        h[j] = so * tanhf(c);
    }
}

// ---------------- warp-per-row linear head (lin_w should be L2-warm from cell2's prefetch) ----------------
template<int N, int WPB, int UNR>
__global__ __launch_bounds__(WPB*32) void k_linw(const float* __restrict__ W,
                                                 const float* __restrict__ x,
                                                 const float* __restrict__ b,
                                                 float* __restrict__ out) {
    constexpr int R = N / 128;
    const int warp = threadIdx.x >> 5, lane = threadIdx.x & 31;
    const int row = blockIdx.x * WPB + warp;

    const float4* __restrict__ xv = (const float4*)x;
    const float4* __restrict__ wr = (const float4*)(W + (size_t)row * N);

    float acc = 0.f;
    #pragma unroll UNR
    for (int k = 0; k < R; k++) {
        int t = lane + 32*k;
        float4 v = xv[t];
        float4 w = wr[t];
        acc += w.x*v.x + w.y*v.y + w.z*v.z + w.w*v.w;
    }
    #pragma unroll
    for (int o = 16; o > 0; o >>= 1) acc += __shfl_xor_sync(0xffffffffu, acc, o);
    if (lane == 0) out[row] = acc + b[row];
}

// ---------------- final: inorm(512) -> leaky -> softmax(512), 3 blocks ----------------
__device__ __forceinline__ float blk_sum512(float v, volatile float* sh) {
    int t = threadIdx.x;
    #pragma unroll
    for (int o = 16; o > 0; o >>= 1) v += __shfl_xor_sync(0xffffffffu, v, o);
    if ((t & 31) == 0) sh[t >> 5] = v;
    __syncthreads();
    if (t == 0) {
        float a = 0.f;
        #pragma unroll
        for (int w = 0; w < 16; w++) a += sh[w];
        sh[16] = a;
    }
    __syncthreads();
    float r = sh[16];
    __syncthreads();
    return r;
}

__device__ __forceinline__ float blk_max512(float v, volatile float* sh) {
    int t = threadIdx.x;
    #pragma unroll
    for (int o = 16; o > 0; o >>= 1) v = fmaxf(v, __shfl_xor_sync(0xffffffffu, v, o));
    if ((t & 31) == 0) sh[t >> 5] = v;
    __syncthreads();
    if (t == 0) {
        float a = -3.4e38f;
        #pragma unroll
        for (int w = 0; w < 16; w++) a = fmaxf(a, sh[w]);
        sh[16] = a;
    }
    __syncthreads();
    float r = sh[16];
    __syncthreads();
    return r;
}

__global__ __launch_bounds__(512) void k_final(float* __restrict__ out) {
    __shared__ float sh[17];
    int b = blockIdx.x;   // 0..2
    int t = threadIdx.x;  // 0..511
    float v = g_o[b*SYM + t];
    float sum = blk_sum512(v, sh);
    float sq  = blk_sum512(v*v, sh);
    float m = sum * (1.0f/SYM);
    float var = sq * (1.0f/SYM) - m*m;
    float xn = (v - m) * rsqrtf(var + EPSF);
    xn = (xn >= 0.f) ? xn : 0.01f*xn;
    float mx = blk_max512(xn, sh);
    float e = expf(xn - mx);
    float se = blk_sum512(e, sh);
    out[b*SYM + t] = e / se;
}

// ---------------- launch ----------------
extern "C" void kernel_launch(void* const* d_in, const int* in_sizes, int n_in,
                              void* d_out, int out_size) {
    const float* wax   = (const float*)d_in[0];
    const float* blw   = (const float*)d_in[1];
    const float* blb   = (const float*)d_in[2];
    const float* w_ih0 = (const float*)d_in[3];
    // d_in[4] = w_hh0 (unused: h0 = 0)
    const float* b_ih0 = (const float*)d_in[5];
    const float* b_hh0 = (const float*)d_in[6];
    const float* w_ih1 = (const float*)d_in[7];
    const float* b_ih1 = (const float*)d_in[9];
    const float* b_hh1 = (const float*)d_in[10];
    const float* w_ih2 = (const float*)d_in[11];
    const float* b_ih2 = (const float*)d_in[13];
    const float* b_hh2 = (const float*)d_in[14];
    const float* lin_w = (const float*)d_in[15];
    const float* lin_b = (const float*)d_in[16];
    float* out = (float*)d_out;

    static float *p_v = nullptr, *p_ha = nullptr, *p_hb = nullptr, *p_o = nullptr;
    if (!p_v) {
        cudaGetSymbolAddress((void**)&p_v,  g_v);
        cudaGetSymbolAddress((void**)&p_ha, g_ha);
        cudaGetSymbolAddress((void**)&p_hb, g_hb);
        cudaGetSymbolAddress((void**)&p_o,  g_o);
    }

    const unsigned GLINES = (unsigned)((size_t)HH*HH*4/128);   // 131072 lines per gate region
    const unsigned LLINES = (unsigned)((size_t)NO*HH*4/128);   // 98304 lines in lin_w

    k_front<<<SYM, 128>>>(wax, blw, blb);

    // cell 0: proven config (NT=192, MINB=8, ITER=18, grid 2048, ~DRAM roofline). No prefetch.
    k_cell<192, 8, HIN, 1, true, false><<<HH, 192>>>(w_ih0, p_v, b_ih0, b_hh0, p_ha,
                                                     nullptr, 0u, nullptr, 0u);

    // cell 1: proven config + bounded prefetch of w_ih2 (i and g gate regions, 33 MB)
    // into cell1's ~2.8 TB/s idle DRAM headroom.
    k_cell<128, 8, HH, 2, true, true><<<HH/2, 128>>>(w_ih1, p_ha, b_ih1, b_hh1, p_hb,
                                                     w_ih2 + (size_t)0*HH*HH, GLINES,
                                                     w_ih2 + (size_t)2*HH*HH, GLINES);

    // cell 2: proven config + prefetch of lin_w (12.6 MB).
    k_cell<128, 8, HH, 2, true, true><<<HH/2, 128>>>(w_ih2, p_hb, b_ih2, b_hh2, p_ha,
                                                     lin_w, LLINES, nullptr, 0u);

    // linear head: warp-per-row (default-cached; should hit L2 now).
    k_linw<HH, 4, 8><<<NO/4, 128>>>(lin_w, p_ha, lin_b, p_o);

    k_final<<<NS, 512>>>(out);
}